// round 1
// baseline (speedup 1.0000x reference)
#include <cuda_runtime.h>
#include <math.h>

#define NB 16
#define NC 128
#define NH 64
#define NW 64
#define NS 17            // 2*8+1 shifts per axis
#define NPOS 289         // 17*17
#define PLANE (NH*NW)    // 4096
#define CHW (NC*PLANE)   // 524288
#define CSPLIT 4
#define CPB (NC/CSPLIT)  // 32 channels per block

// Persistent device scratch (no allocations allowed).
__device__ float d_dot[NB*NB*NPOS];   // raw correlation sums
__device__ float d_part[NB*NPOS];     // raw window energy sums
__device__ float d_gsq[NB];           // ||grd_n||^2

// ---------------------------------------------------------------------------
// Zero the atomic accumulator (must be re-zeroed every launch).
__global__ void k_zero() {
    int i = blockIdx.x * blockDim.x + threadIdx.x;
    if (i < NB*NB*NPOS) d_dot[i] = 0.f;
}

// ---------------------------------------------------------------------------
// Per-grd-sample squared norm.
__global__ void k_gsq(const float* __restrict__ grd) {
    int n = blockIdx.x;
    const float* p = grd + (long long)n * CHW;
    float s = 0.f;
    for (int i = threadIdx.x; i < CHW; i += blockDim.x) {
        float v = p[i];
        s = fmaf(v, v, s);
    }
    __shared__ float r[32];
    for (int o = 16; o > 0; o >>= 1) s += __shfl_down_sync(0xffffffffu, s, o);
    int lane = threadIdx.x & 31, wid = threadIdx.x >> 5;
    if (lane == 0) r[wid] = s;
    __syncthreads();
    if (wid == 0) {
        s = (lane < (int)(blockDim.x >> 5)) ? r[lane] : 0.f;
        for (int o = 16; o > 0; o >>= 1) s += __shfl_down_sync(0xffffffffu, s, o);
        if (lane == 0) d_gsq[n] = s;
    }
}

// ---------------------------------------------------------------------------
// Raw window-energy sums: partical_raw[m,i,j] = sum over rows [i-8,i+56)∩[0,64),
// cols [j-8,j+56)∩[0,64) of sum_c sat[m,c,h,w]^2. Separable (cols then rows).
__global__ void k_part(const float* __restrict__ sat) {
    int m = blockIdx.x;
    __shared__ float e[PLANE];         // per-pixel channel-summed energy
    __shared__ float cw[NS * NH];      // [j][h] column-window sums
    const float* p = sat + (long long)m * CHW;
    for (int idx = threadIdx.x; idx < PLANE; idx += blockDim.x) {
        float s = 0.f;
        for (int c = 0; c < NC; c++) {
            float v = p[c * PLANE + idx];
            s = fmaf(v, v, s);
        }
        e[idx] = s;
    }
    __syncthreads();
    for (int t = threadIdx.x; t < NS * NH; t += blockDim.x) {
        int j = t / NH, h = t % NH;
        int lo = j - 8; if (lo < 0) lo = 0;
        int hi = j - 8 + 64; if (hi > NW) hi = NW;
        float s = 0.f;
        for (int w = lo; w < hi; w++) s += e[h * NW + w];
        cw[j * NH + h] = s;
    }
    __syncthreads();
    for (int t = threadIdx.x; t < NPOS; t += blockDim.x) {
        int i = t / NS, j = t % NS;
        int lo = i - 8; if (lo < 0) lo = 0;
        int hi = i - 8 + 64; if (hi > NH) hi = NH;
        float s = 0.f;
        for (int h = lo; h < hi; h++) s += cw[j * NH + h];
        d_part[m * NPOS + t] = s;
    }
}

// ---------------------------------------------------------------------------
// Main correlation: block = ((m,n) pair, channel quarter).
// Thread (di, hg): di in [0,17), 17 accumulators over dj, rows hg+16*hi.
// satp padded 80x81 (odd stride -> conflict-free shifted-row reads),
// gsh 64x65.
__global__ __launch_bounds__(272)
void k_corr(const float* __restrict__ sat, const float* __restrict__ grd) {
    __shared__ float satp[80 * 81];   // 6480 floats, zero border of 8
    __shared__ float gsh[64 * 65];    // 4160 floats

    int pair = blockIdx.x;
    int m = pair >> 4, n = pair & 15;
    int c0 = blockIdx.y * CPB;
    int t = threadIdx.x;
    int di = t >> 4;     // 0..16
    int hg = t & 15;     // 0..15

    for (int i = t; i < 80 * 81; i += 272) satp[i] = 0.f;

    float acc[NS];
#pragma unroll
    for (int k = 0; k < NS; k++) acc[k] = 0.f;

    const float* sbase = sat + (long long)(m * NC + c0) * PLANE;
    const float* gbase = grd + (long long)(n * NC + c0) * PLANE;

    for (int c = 0; c < CPB; c++) {
        __syncthreads();   // previous compute done / zeroing visible
        for (int idx = t; idx < PLANE; idx += 272) {
            int r = idx >> 6, w = idx & 63;
            satp[(r + 8) * 81 + (w + 8)] = sbase[c * PLANE + idx];
            gsh[r * 65 + w] = gbase[c * PLANE + idx];
        }
        __syncthreads();

#pragma unroll 1
        for (int hi = 0; hi < 4; hi++) {
            int h = hg + 16 * hi;
            const float* srow = &satp[(h + di) * 81];  // h+di in [0,80)
            const float* grow = &gsh[h * 65];
#pragma unroll 1
            for (int w0 = 0; w0 < 64; w0 += 16) {
                float s[32];
#pragma unroll
                for (int k = 0; k < 32; k++) s[k] = srow[w0 + k];
#pragma unroll
                for (int ww = 0; ww < 16; ww++) {
                    float gv = grow[w0 + ww];
#pragma unroll
                    for (int dj = 0; dj < NS; dj++)
                        acc[dj] = fmaf(gv, s[ww + dj], acc[dj]);
                }
            }
        }
    }

    __syncthreads();
    // Reduce over the 16 hg-partials via smem (reuse satp), then one atomic
    // per (di,dj) (only CSPLIT=4 colliders per address).
    float* red = satp;   // needs 272*17 = 4624 <= 6480
#pragma unroll
    for (int dj = 0; dj < NS; dj++) red[t * NS + dj] = acc[dj];
    __syncthreads();
    for (int q = t; q < NPOS; q += 272) {
        int qi = q / NS, qj = q % NS;
        float s = 0.f;
        for (int g = 0; g < 16; g++) s += red[(qi * 16 + g) * NS + qj];
        atomicAdd(&d_dot[pair * NPOS + q], s);
    }
}

// ---------------------------------------------------------------------------
__device__ __forceinline__ float softplusf(float x) {
    return fmaxf(x, 0.f) + log1pf(expf(-fabsf(x)));
}

// Finalize: sim -> dist -> loss terms. One block.
__global__ void k_final(float* __restrict__ out) {
    __shared__ float invp[NB * NPOS];
    __shared__ float gns[NB];
    __shared__ float dist[NB * NB];
    __shared__ float pos[NB];
    __shared__ float red[256];
    __shared__ float rowmin[NB];
    int t = threadIdx.x;

    for (int i = t; i < NB * NPOS; i += 256) invp[i] = rsqrtf(d_part[i]);
    if (t < NB) gns[t] = sqrtf(d_gsq[t]);
    __syncthreads();

    int m = t >> 4, n = t & 15;
    const float* dp = d_dot + t * NPOS;
    const float* ip = invp + m * NPOS;
    float best = -3.4e38f;
    for (int k = 0; k < NPOS; k++) best = fmaxf(best, dp[k] * ip[k]);
    float sim = best / gns[n];
    dist[t] = 2.f - 2.f * sim;
    __syncthreads();

    if (t < NB) pos[t] = dist[t * NB + t];
    __syncthreads();

    float x1 = (pos[n] - dist[t]) * 10.f;   // g2s: pos[None,:] - dist
    float x2 = (pos[m] - dist[t]) * 10.f;   // s2g: pos[:,None] - dist
    red[t] = softplusf(x1) + softplusf(x2);
    if (t < NB) {
        float mn = 3.4e38f;
        for (int k = 0; k < NB; k++) mn = fminf(mn, dist[t * NB + k]);
        rowmin[t] = mn;
    }
    __syncthreads();
    for (int s = 128; s > 0; s >>= 1) {
        if (t < s) red[t] += red[t + s];
        __syncthreads();
    }
    if (t == 0) {
        float pair_n = (float)(NB * (NB - 1));
        float loss = 10.f * (red[0] / (2.f * pair_n));
        float ps = 0.f, ms = 0.f;
        for (int k = 0; k < NB; k++) { ps += pos[k]; ms += rowmin[k]; }
        out[0] = loss;
        out[1] = ps / NB;
        out[2] = ms / NB;
    }
}

// ---------------------------------------------------------------------------
extern "C" void kernel_launch(void* const* d_in, const int* in_sizes, int n_in,
                              void* d_out, int out_size) {
    const float* sat = (const float*)d_in[0];
    const float* grd = (const float*)d_in[1];
    float* out = (float*)d_out;

    k_zero<<<(NB * NB * NPOS + 255) / 256, 256>>>();
    k_gsq<<<NB, 1024>>>(grd);
    k_part<<<NB, 1024>>>(sat);
    k_corr<<<dim3(NB * NB, CSPLIT), 272>>>(sat, grd);
    k_final<<<1, 256>>>(out);
}

// round 2
// speedup vs baseline: 1.0034x; 1.0034x over previous
#include <cuda_runtime.h>
#include <math.h>

#define NB 16
#define NC 128
#define NH 64
#define NW 64
#define NS 17            // 2*8+1 shifts per axis
#define NPOS 289         // 17*17
#define PLANE (NH*NW)    // 4096
#define CHW (NC*PLANE)   // 524288
#define CSPLIT 4
#define CPB (NC/CSPLIT)  // 32 channels per block

// Persistent device scratch (no allocations allowed).
__device__ float d_dot[NB*NB*NPOS];   // raw correlation sums
__device__ float d_part[NB*NPOS];     // raw window energy sums
__device__ float d_gsq[NB];           // ||grd_n||^2

// ---------------------------------------------------------------------------
// Zero the atomic accumulator (must be re-zeroed every launch).
__global__ void k_zero() {
    int i = blockIdx.x * blockDim.x + threadIdx.x;
    if (i < NB*NB*NPOS) d_dot[i] = 0.f;
}

// ---------------------------------------------------------------------------
// Per-grd-sample squared norm.
__global__ void k_gsq(const float* __restrict__ grd) {
    int n = blockIdx.x;
    const float* p = grd + (long long)n * CHW;
    float s = 0.f;
    for (int i = threadIdx.x; i < CHW; i += blockDim.x) {
        float v = p[i];
        s = fmaf(v, v, s);
    }
    __shared__ float r[32];
    for (int o = 16; o > 0; o >>= 1) s += __shfl_down_sync(0xffffffffu, s, o);
    int lane = threadIdx.x & 31, wid = threadIdx.x >> 5;
    if (lane == 0) r[wid] = s;
    __syncthreads();
    if (wid == 0) {
        s = (lane < (int)(blockDim.x >> 5)) ? r[lane] : 0.f;
        for (int o = 16; o > 0; o >>= 1) s += __shfl_down_sync(0xffffffffu, s, o);
        if (lane == 0) d_gsq[n] = s;
    }
}

// ---------------------------------------------------------------------------
// Raw window-energy sums: partical_raw[m,i,j] = sum over rows [i-8,i+56)∩[0,64),
// cols [j-8,j+56)∩[0,64) of sum_c sat[m,c,h,w]^2. Separable (cols then rows).
__global__ void k_part(const float* __restrict__ sat) {
    int m = blockIdx.x;
    __shared__ float e[PLANE];         // per-pixel channel-summed energy
    __shared__ float cw[NS * NH];      // [j][h] column-window sums
    const float* p = sat + (long long)m * CHW;
    for (int idx = threadIdx.x; idx < PLANE; idx += blockDim.x) {
        float s = 0.f;
        for (int c = 0; c < NC; c++) {
            float v = p[c * PLANE + idx];
            s = fmaf(v, v, s);
        }
        e[idx] = s;
    }
    __syncthreads();
    for (int t = threadIdx.x; t < NS * NH; t += blockDim.x) {
        int j = t / NH, h = t % NH;
        int lo = j - 8; if (lo < 0) lo = 0;
        int hi = j - 8 + 64; if (hi > NW) hi = NW;
        float s = 0.f;
        for (int w = lo; w < hi; w++) s += e[h * NW + w];
        cw[j * NH + h] = s;
    }
    __syncthreads();
    for (int t = threadIdx.x; t < NPOS; t += blockDim.x) {
        int i = t / NS, j = t % NS;
        int lo = i - 8; if (lo < 0) lo = 0;
        int hi = i - 8 + 64; if (hi > NH) hi = NH;
        float s = 0.f;
        for (int h = lo; h < hi; h++) s += cw[j * NH + h];
        d_part[m * NPOS + t] = s;
    }
}

// ---------------------------------------------------------------------------
// Main correlation: block = ((m,n) pair, channel quarter).
// Thread (di, hg): di in [0,17), 17 accumulators over dj, rows hg+16*hi.
// satp padded 80x81 (odd stride -> conflict-free shifted-row reads),
// gsh 64x65.
__global__ __launch_bounds__(272)
void k_corr(const float* __restrict__ sat, const float* __restrict__ grd) {
    __shared__ float satp[80 * 81];   // 6480 floats, zero border of 8
    __shared__ float gsh[64 * 65];    // 4160 floats

    int pair = blockIdx.x;
    int m = pair >> 4, n = pair & 15;
    int c0 = blockIdx.y * CPB;
    int t = threadIdx.x;
    int di = t >> 4;     // 0..16
    int hg = t & 15;     // 0..15

    for (int i = t; i < 80 * 81; i += 272) satp[i] = 0.f;

    float acc[NS];
#pragma unroll
    for (int k = 0; k < NS; k++) acc[k] = 0.f;

    const float* sbase = sat + (long long)(m * NC + c0) * PLANE;
    const float* gbase = grd + (long long)(n * NC + c0) * PLANE;

    for (int c = 0; c < CPB; c++) {
        __syncthreads();   // previous compute done / zeroing visible
        for (int idx = t; idx < PLANE; idx += 272) {
            int r = idx >> 6, w = idx & 63;
            satp[(r + 8) * 81 + (w + 8)] = sbase[c * PLANE + idx];
            gsh[r * 65 + w] = gbase[c * PLANE + idx];
        }
        __syncthreads();

#pragma unroll 1
        for (int hi = 0; hi < 4; hi++) {
            int h = hg + 16 * hi;
            const float* srow = &satp[(h + di) * 81];  // h+di in [0,80)
            const float* grow = &gsh[h * 65];
#pragma unroll 1
            for (int w0 = 0; w0 < 64; w0 += 16) {
                float s[32];
#pragma unroll
                for (int k = 0; k < 32; k++) s[k] = srow[w0 + k];
#pragma unroll
                for (int ww = 0; ww < 16; ww++) {
                    float gv = grow[w0 + ww];
#pragma unroll
                    for (int dj = 0; dj < NS; dj++)
                        acc[dj] = fmaf(gv, s[ww + dj], acc[dj]);
                }
            }
        }
    }

    __syncthreads();
    // Reduce over the 16 hg-partials via smem (reuse satp), then one atomic
    // per (di,dj) (only CSPLIT=4 colliders per address).
    float* red = satp;   // needs 272*17 = 4624 <= 6480
#pragma unroll
    for (int dj = 0; dj < NS; dj++) red[t * NS + dj] = acc[dj];
    __syncthreads();
    for (int q = t; q < NPOS; q += 272) {
        int qi = q / NS, qj = q % NS;
        float s = 0.f;
        for (int g = 0; g < 16; g++) s += red[(qi * 16 + g) * NS + qj];
        atomicAdd(&d_dot[pair * NPOS + q], s);
    }
}

// ---------------------------------------------------------------------------
__device__ __forceinline__ float softplusf(float x) {
    return fmaxf(x, 0.f) + log1pf(expf(-fabsf(x)));
}

// Finalize: sim -> dist -> loss terms. One block.
__global__ void k_final(float* __restrict__ out) {
    __shared__ float invp[NB * NPOS];
    __shared__ float gns[NB];
    __shared__ float dist[NB * NB];
    __shared__ float pos[NB];
    __shared__ float red[256];
    __shared__ float rowmin[NB];
    int t = threadIdx.x;

    for (int i = t; i < NB * NPOS; i += 256) invp[i] = rsqrtf(d_part[i]);
    if (t < NB) gns[t] = sqrtf(d_gsq[t]);
    __syncthreads();

    int m = t >> 4, n = t & 15;
    const float* dp = d_dot + t * NPOS;
    const float* ip = invp + m * NPOS;
    float best = -3.4e38f;
    for (int k = 0; k < NPOS; k++) best = fmaxf(best, dp[k] * ip[k]);
    float sim = best / gns[n];
    dist[t] = 2.f - 2.f * sim;
    __syncthreads();

    if (t < NB) pos[t] = dist[t * NB + t];
    __syncthreads();

    float x1 = (pos[n] - dist[t]) * 10.f;   // g2s: pos[None,:] - dist
    float x2 = (pos[m] - dist[t]) * 10.f;   // s2g: pos[:,None] - dist
    red[t] = softplusf(x1) + softplusf(x2);
    if (t < NB) {
        float mn = 3.4e38f;
        for (int k = 0; k < NB; k++) mn = fminf(mn, dist[t * NB + k]);
        rowmin[t] = mn;
    }
    __syncthreads();
    for (int s = 128; s > 0; s >>= 1) {
        if (t < s) red[t] += red[t + s];
        __syncthreads();
    }
    if (t == 0) {
        float pair_n = (float)(NB * (NB - 1));
        float loss = 10.f * (red[0] / (2.f * pair_n));
        float ps = 0.f, ms = 0.f;
        for (int k = 0; k < NB; k++) { ps += pos[k]; ms += rowmin[k]; }
        out[0] = loss;
        out[1] = ps / NB;
        out[2] = ms / NB;
    }
}

// ---------------------------------------------------------------------------
extern "C" void kernel_launch(void* const* d_in, const int* in_sizes, int n_in,
                              void* d_out, int out_size) {
    const float* sat = (const float*)d_in[0];
    const float* grd = (const float*)d_in[1];
    float* out = (float*)d_out;

    k_zero<<<(NB * NB * NPOS + 255) / 256, 256>>>();
    k_gsq<<<NB, 1024>>>(grd);
    k_part<<<NB, 1024>>>(sat);
    k_corr<<<dim3(NB * NB, CSPLIT), 272>>>(sat, grd);
    k_final<<<1, 256>>>(out);
}